// round 14
// baseline (speedup 1.0000x reference)
#include <cuda_runtime.h>
#include <cuda_fp16.h>
#include <cstdint>
#include <math.h>

// Problem constants
#define NN   32768
#define KK   1024
#define QE   16777216

// GEMM tiling: CTA = 128 rows x 128 codes, 256 thr = 8 warps (4M x 2N)
// KC = 64 channels per slab, 8 slabs, 2 smem stages.
#define M_TILE 128
#define N_TILE 128
#define K_SLABS 8              // 512 ch / 64 per slab
#define ROW_STRIDE 144         // 128B data + 16B pad (9x16B -> conflict-free ldsm)
#define A_PHASE_BYTES (128 * ROW_STRIDE)            // 18432
#define STAGE_BYTES (3 * A_PHASE_BYTES)             // 2 A planes + B = 55296
#define N_STAGES 2
#define GEMM_SMEM (N_STAGES * STAGE_BYTES)          // 110592 (x2 CTAs = 221184)
#define PREP_SMEM (65664 + 2048)

// Scratch (device globals; allocation-free). Slab-major (32ch source slabs):
__device__ uint32_t g_hi[16 * NN * 16];
__device__ uint32_t g_mid[16 * NN * 16];
__device__ uint32_t g_cbh[16 * KK * 16];   // fp16 codebook [slab][code][16 u32]
__device__ float g_x2[NN];
__device__ unsigned long long g_best[NN];
__device__ int g_cnt[KK];

__device__ __forceinline__ uint32_t smem_u32(const void* p) {
    return (uint32_t)__cvta_generic_to_shared(p);
}

#define LDSM4(r0, r1, r2, r3, addr)                                           \
    asm volatile("ldmatrix.sync.aligned.m8n8.x4.shared.b16 {%0,%1,%2,%3}, [%4];" \
                 : "=r"(r0), "=r"(r1), "=r"(r2), "=r"(r3) : "r"(addr))

#define MMA16816(C, A, B0, B1)                                                \
    asm volatile("mma.sync.aligned.m16n8k16.row.col.f32.f16.f16.f32 "         \
                 "{%0,%1,%2,%3},{%4,%5,%6,%7},{%8,%9},{%0,%1,%2,%3};"         \
                 : "+f"((C)[0]), "+f"((C)[1]), "+f"((C)[2]), "+f"((C)[3])     \
                 : "r"((A)[0]), "r"((A)[1]), "r"((A)[2]), "r"((A)[3]),        \
                   "r"(B0), "r"(B1))

#define CP_ASYNC16(dst, src)                                                  \
    asm volatile("cp.async.cg.shared.global [%0], [%1], 16;" :: "r"(dst), "l"(src))
#define CP_COMMIT() asm volatile("cp.async.commit_group;")
#define CP_WAIT0()  asm volatile("cp.async.wait_group 0;")

// ---------------------------------------------------------------------------
// init + codebook fp32 (+-1) -> fp16 (exact) slab-major, fused
// ---------------------------------------------------------------------------
__global__ void init_cb_kernel(const float* __restrict__ cb) {
    int i = blockIdx.x * 256 + threadIdx.x;   // 0..262143: code*256 + cw
    int code = i >> 8, cw = i & 255;
    float2 v = ((const float2*)cb)[i];
    __half2 h2 = __floats2half2_rn(v.x, v.y);
    uint32_t u; memcpy(&u, &h2, 4);
    g_cbh[(((size_t)(cw >> 4)) * KK + code) * 16 + (cw & 15)] = u;
    if (i < NN) g_best[i] = 0xFFFFFFFFFFFFFFFFull;
    if (i < KK) g_cnt[i] = 0;
}

// ---------------------------------------------------------------------------
// prep: xs = tanh(50x) via FMA-only exp2 + Newton rcp, 2-way fp16 split,
// transpose slab-major, ||xs||^2 + 512.
// ---------------------------------------------------------------------------
__global__ void __launch_bounds__(512, 3) prep_kernel(const float* __restrict__ x) {
    extern __shared__ char sm[];
    uint32_t* s_hm = (uint32_t*)sm;             // [32][513]  (hi | mid<<16)
    float* s_red = (float*)(sm + 65664);        // [512]

    int tid = threadIdx.x;
    int b   = blockIdx.x >> 5;
    int p0  = (blockIdx.x & 31) * 32;
    int p   = tid & 31;
    int cg  = tid >> 5;         // 0..15

    float acc = 0.0f;
#pragma unroll 4
    for (int j = 0; j < 32; j++) {
        int c = j * 16 + cg;
        float v = x[(b * 512 + c) * 1024 + p0 + p];
        float t = fmaxf(-144.26950408889634f * fabsf(v), -30.0f);
        float kf = t + 12582912.0f;
        int   ni = __float_as_int(kf) - 0x4B400000;
        float f  = t - (kf - 12582912.0f);
        float pe = 1.52527338e-5f;
        pe = fmaf(pe, f, 1.54035304e-4f);
        pe = fmaf(pe, f, 1.33335581e-3f);
        pe = fmaf(pe, f, 9.61812911e-3f);
        pe = fmaf(pe, f, 5.55041087e-2f);
        pe = fmaf(pe, f, 2.40226507e-1f);
        pe = fmaf(pe, f, 6.93147181e-1f);
        pe = fmaf(pe, f, 1.0f);
        float m = __int_as_float(__float_as_int(pe) + (ni << 23));
        float den = 1.0f + m;
        float r = fmaf(-0.5f, den, 1.45710678f);
        r = r * fmaf(-den, r, 2.0f);
        r = r * fmaf(-den, r, 2.0f);
        r = r * fmaf(-den, r, 2.0f);
        float w = (1.0f - m) * r;
        float xs = copysignf(w, v);
        acc = fmaf(w, w, acc);
        __half h = __float2half_rn(xs);
        float r1 = xs - __half2float(h);
        __half md = __float2half_rn(r1);
        s_hm[p * 513 + c] = (uint32_t)__half_as_ushort(h)
                          | ((uint32_t)__half_as_ushort(md) << 16);
    }
    s_red[tid] = acc;
    __syncthreads();

    if (tid < 32) {
        float t = 0.0f;
#pragma unroll
        for (int g = 0; g < 16; g++) t += s_red[g * 32 + tid];
        g_x2[b * 1024 + p0 + tid] = t + 512.0f;
    }

    int nb = b * 1024 + p0;
#pragma unroll 4
    for (int t = tid; t < 32 * 256; t += 512) {
        int r  = t >> 8;
        int cw = t & 255;
        uint32_t hm0 = s_hm[r * 513 + 2 * cw];
        uint32_t hm1 = s_hm[r * 513 + 2 * cw + 1];
        uint32_t hi_pair  = (hm0 & 0xffffu) | (hm1 << 16);
        uint32_t mid_pair = (hm0 >> 16) | (hm1 & 0xffff0000u);
        size_t gi = (((size_t)(cw >> 4)) * NN + nb + r) * 16 + (cw & 15);
        g_hi[gi]  = hi_pair;
        g_mid[gi] = mid_pair;
    }
}

// ---------------------------------------------------------------------------
// GEMM + fused argmin. grid = 256 M-tiles x 8 N-chunks (nc in low 3 bits).
// 256 threads = 8 warps (4M x 2N), warp tile 32x64, 2 fp16 split planes.
// KC=64: 8 slabs, 2-stage cp.async pipeline, one __syncthreads per slab.
// ---------------------------------------------------------------------------
__global__ void __launch_bounds__(256, 2) gemm_hmma_kernel() {
    extern __shared__ char sm[];
    uint32_t smb = smem_u32(sm);

    int tid = threadIdx.x;
    int lane = tid & 31;
    int wid = tid >> 5;
    int wy = wid & 3;
    int wx = wid >> 2;          // 0..1
    int bid = blockIdx.x;
    int rowbase = (bid >> 3) * M_TILE;
    int colchunk = (bid & 7) * N_TILE;

    uint32_t tbaseA = (uint32_t)((wy * 32 + ((lane >> 3) & 1) * 8 + (lane & 7)) * ROW_STRIDE
                                 + (lane >> 4) * 16);
    uint32_t tbaseB = (uint32_t)(((lane >> 4) * 8 + (lane & 7)) * ROW_STRIDE
                                 + ((lane >> 3) & 1) * 16);

    const char* gA[2] = { (const char*)g_hi, (const char*)g_mid };

    float x2v[4];
#pragma unroll
    for (int s = 0; s < 4; s++)
        x2v[s] = g_x2[rowbase + wy * 32 + (lane >> 2) + ((s & 1) ? 8 : 0) + (s >> 1) * 16];

    float bD[4] = {INFINITY, INFINITY, INFINITY, INFINITY};
    int   bI[4] = {0, 0, 0, 0};

    float acc[2][8][4];
#pragma unroll
    for (int m = 0; m < 2; m++)
#pragma unroll
        for (int nf = 0; nf < 8; nf++)
#pragma unroll
            for (int j = 0; j < 4; j++) acc[m][nf][j] = 0.0f;

// 3072 16B chunks per 64ch slab: A 2 planes x128r x8 = 2048, B 128r x8 = 1024.
// source: 64ch slab `slab` = source 32ch slabs (2*slab + (c16>>2)).
#define ISSUE_SLAB(slab, stage)                                               \
    {                                                                         \
        uint32_t dstbase = smb + (stage) * STAGE_BYTES;                       \
        _Pragma("unroll")                                                     \
        for (int i = 0; i < 12; i++) {                                        \
            int id = tid + i * 256;                                           \
            if (id < 2048) {                                                  \
                int part = id >> 10;                                          \
                int r = (id >> 3) & 127;                                      \
                int c16 = id & 7;                                             \
                uint32_t dst = dstbase + part * A_PHASE_BYTES                 \
                             + r * ROW_STRIDE + c16 * 16;                     \
                const char* src = gA[part]                                    \
                    + ((size_t)(2 * (slab) + (c16 >> 2)) * NN + rowbase + r) * 64 \
                    + (c16 & 3) * 16;                                         \
                CP_ASYNC16(dst, src);                                         \
            } else {                                                          \
                int id2 = id - 2048;                                          \
                int r = id2 >> 3;                                             \
                int c16 = id2 & 7;                                            \
                uint32_t dst = dstbase + 2 * A_PHASE_BYTES                    \
                             + r * ROW_STRIDE + c16 * 16;                     \
                const char* src = (const char*)g_cbh                          \
                    + ((size_t)(2 * (slab) + (c16 >> 2)) * KK + colchunk + r) * 64 \
                    + (c16 & 3) * 16;                                         \
                CP_ASYNC16(dst, src);                                         \
            }                                                                 \
        }                                                                     \
        CP_COMMIT();                                                          \
    }

    ISSUE_SLAB(0, 0);

    for (int s = 0; s < K_SLABS; s++) {
        CP_WAIT0();
        __syncthreads();
        // issue s+1 into the other stage (freed: all warps done reading it
        // during compute of s-1, guaranteed by the sync above)
        if (s + 1 < K_SLABS) ISSUE_SLAB(s + 1, (s + 1) & 1);

        uint32_t sA = smb + (s & 1) * STAGE_BYTES;
        uint32_t sB = sA + 2 * A_PHASE_BYTES;
#pragma unroll
        for (int kk = 0; kk < 4; kk++) {
            uint32_t b[8][2];
#pragma unroll
            for (int q = 0; q < 4; q++) {
                uint32_t addr = sB + (uint32_t)((wx * 64 + q * 16) * ROW_STRIDE)
                              + tbaseB + kk * 32;
                LDSM4(b[2 * q][0], b[2 * q][1], b[2 * q + 1][0], b[2 * q + 1][1], addr);
            }
#pragma unroll
            for (int p = 0; p < 2; p++) {
                uint32_t a0[4], a1[4];
                uint32_t aaddr = sA + p * A_PHASE_BYTES + tbaseA + kk * 32;
                LDSM4(a0[0], a0[1], a0[2], a0[3], aaddr);
                LDSM4(a1[0], a1[1], a1[2], a1[3], aaddr + 16 * ROW_STRIDE);
#pragma unroll
                for (int nf = 0; nf < 8; nf++) {
                    MMA16816(acc[0][nf], a0, b[nf][0], b[nf][1]);
                    MMA16816(acc[1][nf], a1, b[nf][0], b[nf][1]);
                }
            }
        }
    }
#undef ISSUE_SLAB

    // fused argmin over this chunk's 128 columns (ascending index)
    int colbase = colchunk + wx * 64 + (lane & 3) * 2;
#pragma unroll
    for (int nf = 0; nf < 8; nf++) {
        int cidx = colbase + nf * 8;
#pragma unroll
        for (int m = 0; m < 2; m++) {
            float d0 = fmaf(-2.0f, acc[m][nf][0], x2v[m * 2]);
            float d1 = fmaf(-2.0f, acc[m][nf][1], x2v[m * 2]);
            float d2 = fmaf(-2.0f, acc[m][nf][2], x2v[m * 2 + 1]);
            float d3 = fmaf(-2.0f, acc[m][nf][3], x2v[m * 2 + 1]);
            if (d0 < bD[m * 2])     { bD[m * 2] = d0;     bI[m * 2] = cidx; }
            if (d1 < bD[m * 2])     { bD[m * 2] = d1;     bI[m * 2] = cidx + 1; }
            if (d2 < bD[m * 2 + 1]) { bD[m * 2 + 1] = d2; bI[m * 2 + 1] = cidx; }
            if (d3 < bD[m * 2 + 1]) { bD[m * 2 + 1] = d3; bI[m * 2 + 1] = cidx + 1; }
        }
    }

#pragma unroll
    for (int off = 1; off <= 2; off <<= 1) {
#pragma unroll
        for (int s = 0; s < 4; s++) {
            float od = __shfl_xor_sync(0xffffffffu, bD[s], off);
            int   oi = __shfl_xor_sync(0xffffffffu, bI[s], off);
            if (od < bD[s] || (od == bD[s] && oi < bI[s])) { bD[s] = od; bI[s] = oi; }
        }
    }

    if ((lane & 3) == 0) {
#pragma unroll
        for (int s = 0; s < 4; s++) {
            int row = rowbase + wy * 32 + (lane >> 2) + ((s & 1) ? 8 : 0) + (s >> 1) * 16;
            uint32_t u = __float_as_uint(bD[s]);
            u = (u & 0x80000000u) ? ~u : (u | 0x80000000u);
            unsigned long long key = ((unsigned long long)u << 32) | (unsigned)bI[s];
            atomicMin(&g_best[row], key);
        }
    }
}

// ---------------------------------------------------------------------------
// gather: smem-staged, 512 threads (unchanged from R12/R13 best).
// ---------------------------------------------------------------------------
__global__ void __launch_bounds__(512) gather_kernel(const float* __restrict__ cb,
                                                     float* __restrict__ out) {
    __shared__ float4 srow[32 * 128];   // 64KB, cf ^ (nl&7) swizzle

    int tid = threadIdx.x;
    int lane = tid & 31;
    int w = tid >> 5;           // 0..15
    int nbase = blockIdx.x * 32;

#pragma unroll
    for (int k = 0; k < 2; k++) {
        int nl = w * 2 + k;
        int idx = (int)(unsigned)(g_best[nbase + nl] & 0xffffffffu);
        const float4* src = (const float4*)cb + idx * 128;
        int sw = nl & 7;
#pragma unroll
        for (int j = 0; j < 4; j++) {
            int cf = lane + j * 32;
            srow[nl * 128 + (cf ^ sw)] = __ldg(src + cf);
        }
    }
    __syncthreads();

    {
        int nl = lane;
        int n = nbase + nl;
        int b = n >> 10, p = n & 1023;
        int sw = nl & 7;
        float* obase = out + ((size_t)b * 512) * 1024 + p;
#pragma unroll
        for (int j = 0; j < 8; j++) {
            int cf = w * 8 + j;
            float4 v = srow[nl * 128 + (cf ^ sw)];
            float* o = obase + (size_t)(cf * 4) * 1024;
            __stcs(o,        v.x);
            __stcs(o + 1024, v.y);
            __stcs(o + 2048, v.z);
            __stcs(o + 3072, v.w);
        }
    }
}

// ---------------------------------------------------------------------------
__global__ void hist_kernel() {
    __shared__ int h[KK];
    int tid = threadIdx.x;
    for (int i = tid; i < KK; i += 256) h[i] = 0;
    __syncthreads();
    int base = blockIdx.x * 1024;
    for (int i = tid; i < 1024; i += 256)
        atomicAdd(&h[(int)(unsigned)(g_best[base + i] & 0xffffffffu)], 1);
    __syncthreads();
    for (int i = tid; i < KK; i += 256) if (h[i]) atomicAdd(&g_cnt[i], h[i]);
}

__global__ void entropy_kernel(float* __restrict__ out_scalars) {
    __shared__ float s[256];
    int tid = threadIdx.x;
    float acc = 0.0f;
    for (int k = tid; k < KK; k += 256) {
        int c = g_cnt[k];
        if (c > 0) {
            float p = (float)c / 32768.0f;
            acc += p * logf(p);
        }
    }
    s[tid] = acc;
    __syncthreads();
    for (int o = 128; o > 0; o >>= 1) {
        if (tid < o) s[tid] += s[tid + o];
        __syncthreads();
    }
    if (tid == 0) {
        float entropy = -s[0];
        float perp = expf(entropy);
        float pl = 1.0f / perp;
        out_scalars[0] = pl;
        out_scalars[1] = 0.25f * pl;
    }
}

// ---------------------------------------------------------------------------
extern "C" void kernel_launch(void* const* d_in, const int* in_sizes, int n_in,
                              void* d_out, int out_size) {
    const float* x  = (const float*)d_in[0];
    const float* cb = (const float*)d_in[1];
    float* out = (float*)d_out;

    cudaFuncSetAttribute(prep_kernel, cudaFuncAttributeMaxDynamicSharedMemorySize, PREP_SMEM);
    cudaFuncSetAttribute(gemm_hmma_kernel, cudaFuncAttributeMaxDynamicSharedMemorySize, GEMM_SMEM);

    init_cb_kernel<<<1024, 256>>>(cb);
    prep_kernel<<<1024, 512, PREP_SMEM>>>(x);
    gemm_hmma_kernel<<<(NN / M_TILE) * (KK / N_TILE), 256, GEMM_SMEM>>>();
    gather_kernel<<<NN / 32, 512>>>(cb, out);
    hist_kernel<<<NN / 1024, 256>>>();
    if (out_size >= QE + 2) {
        entropy_kernel<<<1, 256>>>(out + QE);
    }
}

// round 15
// speedup vs baseline: 1.0322x; 1.0322x over previous
#include <cuda_runtime.h>
#include <cuda_fp16.h>
#include <cstdint>
#include <math.h>

// Problem constants
#define NN   32768
#define KK   1024
#define QE   16777216

// GEMM tiling (R12 best): CTA = 128 rows x 128 codes, 256 thr = 8 warps (4M x 2N)
#define M_TILE 128
#define N_TILE 128
#define K_SLABS 16             // 512 ch / 32 per slab
#define ROW_STRIDE 80          // 64B data + 16B pad (conflict-free ldsm)
#define A_PHASE_BYTES (128 * ROW_STRIDE)            // 10240
#define STAGE_BYTES (3 * A_PHASE_BYTES)             // 2 A planes + B = 30720
#define N_STAGES 3
#define GEMM_SMEM (N_STAGES * STAGE_BYTES)          // 92160 (x2 CTAs/SM)
#define PREP_SMEM (65664 + 2048)

// Scratch (device globals; allocation-free). Slab-major:
__device__ uint32_t g_hi[16 * NN * 16];
__device__ uint32_t g_mid[16 * NN * 16];
__device__ uint32_t g_cbh[16 * KK * 16];   // fp16 codebook [slab][code][16 u32]
__device__ float g_x2[NN];
__device__ unsigned long long g_best[NN];
__device__ int g_cnt[KK];

__device__ __forceinline__ uint32_t smem_u32(const void* p) {
    return (uint32_t)__cvta_generic_to_shared(p);
}

#define LDSM4(r0, r1, r2, r3, addr)                                           \
    asm volatile("ldmatrix.sync.aligned.m8n8.x4.shared.b16 {%0,%1,%2,%3}, [%4];" \
                 : "=r"(r0), "=r"(r1), "=r"(r2), "=r"(r3) : "r"(addr))

#define MMA16816(C, A, B0, B1)                                                \
    asm volatile("mma.sync.aligned.m16n8k16.row.col.f32.f16.f16.f32 "         \
                 "{%0,%1,%2,%3},{%4,%5,%6,%7},{%8,%9},{%0,%1,%2,%3};"         \
                 : "+f"((C)[0]), "+f"((C)[1]), "+f"((C)[2]), "+f"((C)[3])     \
                 : "r"((A)[0]), "r"((A)[1]), "r"((A)[2]), "r"((A)[3]),        \
                   "r"(B0), "r"(B1))

#define CP_ASYNC16(dst, src)                                                  \
    asm volatile("cp.async.cg.shared.global [%0], [%1], 16;" :: "r"(dst), "l"(src))
#define CP_COMMIT() asm volatile("cp.async.commit_group;")
#define CP_WAIT1()  asm volatile("cp.async.wait_group 1;")
#define CP_WAIT0()  asm volatile("cp.async.wait_group 0;")

// ---------------------------------------------------------------------------
// init + codebook fp32 (+-1) -> fp16 (exact) slab-major, fused
// ---------------------------------------------------------------------------
__global__ void init_cb_kernel(const float* __restrict__ cb) {
    int i = blockIdx.x * 256 + threadIdx.x;   // 0..262143: code*256 + cw
    int code = i >> 8, cw = i & 255;
    float2 v = ((const float2*)cb)[i];
    __half2 h2 = __floats2half2_rn(v.x, v.y);
    uint32_t u; memcpy(&u, &h2, 4);
    g_cbh[(((size_t)(cw >> 4)) * KK + code) * 16 + (cw & 15)] = u;
    if (i < NN) g_best[i] = 0xFFFFFFFFFFFFFFFFull;
    if (i < KK) g_cnt[i] = 0;
}

// ---------------------------------------------------------------------------
// prep: xs = tanh(50x) via FMA-only exp2 + Newton rcp, 2-way fp16 split,
// transpose slab-major, ||xs||^2 + 512.
// ---------------------------------------------------------------------------
__global__ void __launch_bounds__(512, 3) prep_kernel(const float* __restrict__ x) {
    extern __shared__ char sm[];
    uint32_t* s_hm = (uint32_t*)sm;             // [32][513]  (hi | mid<<16)
    float* s_red = (float*)(sm + 65664);        // [512]

    int tid = threadIdx.x;
    int b   = blockIdx.x >> 5;
    int p0  = (blockIdx.x & 31) * 32;
    int p   = tid & 31;
    int cg  = tid >> 5;         // 0..15

    float acc = 0.0f;
#pragma unroll 4
    for (int j = 0; j < 32; j++) {
        int c = j * 16 + cg;
        float v = x[(b * 512 + c) * 1024 + p0 + p];
        float t = fmaxf(-144.26950408889634f * fabsf(v), -30.0f);
        float kf = t + 12582912.0f;
        int   ni = __float_as_int(kf) - 0x4B400000;
        float f  = t - (kf - 12582912.0f);
        float pe = 1.52527338e-5f;
        pe = fmaf(pe, f, 1.54035304e-4f);
        pe = fmaf(pe, f, 1.33335581e-3f);
        pe = fmaf(pe, f, 9.61812911e-3f);
        pe = fmaf(pe, f, 5.55041087e-2f);
        pe = fmaf(pe, f, 2.40226507e-1f);
        pe = fmaf(pe, f, 6.93147181e-1f);
        pe = fmaf(pe, f, 1.0f);
        float m = __int_as_float(__float_as_int(pe) + (ni << 23));
        float den = 1.0f + m;
        float r = fmaf(-0.5f, den, 1.45710678f);
        r = r * fmaf(-den, r, 2.0f);
        r = r * fmaf(-den, r, 2.0f);
        r = r * fmaf(-den, r, 2.0f);
        float w = (1.0f - m) * r;
        float xs = copysignf(w, v);
        acc = fmaf(w, w, acc);
        __half h = __float2half_rn(xs);
        float r1 = xs - __half2float(h);
        __half md = __float2half_rn(r1);
        s_hm[p * 513 + c] = (uint32_t)__half_as_ushort(h)
                          | ((uint32_t)__half_as_ushort(md) << 16);
    }
    s_red[tid] = acc;
    __syncthreads();

    if (tid < 32) {
        float t = 0.0f;
#pragma unroll
        for (int g = 0; g < 16; g++) t += s_red[g * 32 + tid];
        g_x2[b * 1024 + p0 + tid] = t + 512.0f;
    }

    int nb = b * 1024 + p0;
#pragma unroll 4
    for (int t = tid; t < 32 * 256; t += 512) {
        int r  = t >> 8;
        int cw = t & 255;
        uint32_t hm0 = s_hm[r * 513 + 2 * cw];
        uint32_t hm1 = s_hm[r * 513 + 2 * cw + 1];
        uint32_t hi_pair  = (hm0 & 0xffffu) | (hm1 << 16);
        uint32_t mid_pair = (hm0 >> 16) | (hm1 & 0xffff0000u);
        size_t gi = (((size_t)(cw >> 4)) * NN + nb + r) * 16 + (cw & 15);
        g_hi[gi]  = hi_pair;
        g_mid[gi] = mid_pair;
    }
}

// ---------------------------------------------------------------------------
// GEMM + fused argmin (R12 best). grid = 256 M-tiles x 8 N-chunks.
// 256 threads = 8 warps (4M x 2N), warp tile 32x64, 2 fp16 split planes.
// 3-stage cp.async pipeline, one __syncthreads per slab, 2 CTAs/SM.
// ---------------------------------------------------------------------------
__global__ void __launch_bounds__(256, 2) gemm_hmma_kernel() {
    extern __shared__ char sm[];
    uint32_t smb = smem_u32(sm);

    int tid = threadIdx.x;
    int lane = tid & 31;
    int wid = tid >> 5;
    int wy = wid & 3;
    int wx = wid >> 2;          // 0..1
    int bid = blockIdx.x;
    int rowbase = (bid >> 3) * M_TILE;
    int colchunk = (bid & 7) * N_TILE;

    uint32_t tbaseA = (uint32_t)((wy * 32 + ((lane >> 3) & 1) * 8 + (lane & 7)) * ROW_STRIDE
                                 + (lane >> 4) * 16);
    uint32_t tbaseB = (uint32_t)(((lane >> 4) * 8 + (lane & 7)) * ROW_STRIDE
                                 + ((lane >> 3) & 1) * 16);

    const char* gA[2] = { (const char*)g_hi, (const char*)g_mid };

    float x2v[4];
#pragma unroll
    for (int s = 0; s < 4; s++)
        x2v[s] = g_x2[rowbase + wy * 32 + (lane >> 2) + ((s & 1) ? 8 : 0) + (s >> 1) * 16];

    float bD[4] = {INFINITY, INFINITY, INFINITY, INFINITY};
    int   bI[4] = {0, 0, 0, 0};

    float acc[2][8][4];
#pragma unroll
    for (int m = 0; m < 2; m++)
#pragma unroll
        for (int nf = 0; nf < 8; nf++)
#pragma unroll
            for (int j = 0; j < 4; j++) acc[m][nf][j] = 0.0f;

// 1536 16B chunks per slab: A 2 planes x128r x4c = 1024, B 128r x4c = 512.
#define ISSUE_SLAB(slab, stage)                                               \
    {                                                                         \
        uint32_t dstbase = smb + (stage) * STAGE_BYTES;                       \
        _Pragma("unroll")                                                     \
        for (int i = 0; i < 6; i++) {                                         \
            int id = tid + i * 256;                                           \
            if (id < 1024) {                                                  \
                int part = id >> 9;                                           \
                int r = (id >> 2) & 127;                                      \
                int c = id & 3;                                               \
                uint32_t dst = dstbase + part * A_PHASE_BYTES                 \
                             + r * ROW_STRIDE + c * 16;                       \
                const char* src = gA[part]                                    \
                    + ((size_t)(slab) * NN + rowbase + r) * 64 + c * 16;      \
                CP_ASYNC16(dst, src);                                         \
            } else {                                                          \
                int id2 = id - 1024;                                          \
                int r = id2 >> 2;                                             \
                int c = id2 & 3;                                              \
                uint32_t dst = dstbase + 2 * A_PHASE_BYTES                    \
                             + r * ROW_STRIDE + c * 16;                       \
                const char* src = (const char*)g_cbh                          \
                    + ((size_t)(slab) * KK + colchunk + r) * 64 + c * 16;     \
                CP_ASYNC16(dst, src);                                         \
            }                                                                 \
        }                                                                     \
        CP_COMMIT();                                                          \
    }

    // prologue: two slabs in flight
    ISSUE_SLAB(0, 0);
    ISSUE_SLAB(1, 1);

    int st0 = 0;                // stage of slab s
    for (int s = 0; s < K_SLABS; s++) {
        if (s + 1 < K_SLABS) { CP_WAIT1(); } else { CP_WAIT0(); }
        __syncthreads();

        // issue s+2 into the stage freed by slab s-1 (readers done at the sync)
        if (s + 2 < K_SLABS) {
            int st2 = st0 + 2; if (st2 >= N_STAGES) st2 -= N_STAGES;
            ISSUE_SLAB(s + 2, st2);
        }

        uint32_t sA = smb + st0 * STAGE_BYTES;
        uint32_t sB = sA + 2 * A_PHASE_BYTES;
#pragma unroll
        for (int kk = 0; kk < 2; kk++) {
            uint32_t b[8][2];
#pragma unroll
            for (int q = 0; q < 4; q++) {
                uint32_t addr = sB + (uint32_t)((wx * 64 + q * 16) * ROW_STRIDE)
                              + tbaseB + kk * 32;
                LDSM4(b[2 * q][0], b[2 * q][1], b[2 * q + 1][0], b[2 * q + 1][1], addr);
            }
#pragma unroll
            for (int p = 0; p < 2; p++) {
                uint32_t a0[4], a1[4];
                uint32_t aaddr = sA + p * A_PHASE_BYTES + tbaseA + kk * 32;
                LDSM4(a0[0], a0[1], a0[2], a0[3], aaddr);
                LDSM4(a1[0], a1[1], a1[2], a1[3], aaddr + 16 * ROW_STRIDE);
#pragma unroll
                for (int nf = 0; nf < 8; nf++) {
                    MMA16816(acc[0][nf], a0, b[nf][0], b[nf][1]);
                    MMA16816(acc[1][nf], a1, b[nf][0], b[nf][1]);
                }
            }
        }
        st0 = st0 + 1; if (st0 >= N_STAGES) st0 -= N_STAGES;
    }
#undef ISSUE_SLAB

    // fused argmin over this chunk's 128 columns (ascending index)
    int colbase = colchunk + wx * 64 + (lane & 3) * 2;
#pragma unroll
    for (int nf = 0; nf < 8; nf++) {
        int cidx = colbase + nf * 8;
#pragma unroll
        for (int m = 0; m < 2; m++) {
            float d0 = fmaf(-2.0f, acc[m][nf][0], x2v[m * 2]);
            float d1 = fmaf(-2.0f, acc[m][nf][1], x2v[m * 2]);
            float d2 = fmaf(-2.0f, acc[m][nf][2], x2v[m * 2 + 1]);
            float d3 = fmaf(-2.0f, acc[m][nf][3], x2v[m * 2 + 1]);
            if (d0 < bD[m * 2])     { bD[m * 2] = d0;     bI[m * 2] = cidx; }
            if (d1 < bD[m * 2])     { bD[m * 2] = d1;     bI[m * 2] = cidx + 1; }
            if (d2 < bD[m * 2 + 1]) { bD[m * 2 + 1] = d2; bI[m * 2 + 1] = cidx; }
            if (d3 < bD[m * 2 + 1]) { bD[m * 2 + 1] = d3; bI[m * 2 + 1] = cidx + 1; }
        }
    }

#pragma unroll
    for (int off = 1; off <= 2; off <<= 1) {
#pragma unroll
        for (int s = 0; s < 4; s++) {
            float od = __shfl_xor_sync(0xffffffffu, bD[s], off);
            int   oi = __shfl_xor_sync(0xffffffffu, bI[s], off);
            if (od < bD[s] || (od == bD[s] && oi < bI[s])) { bD[s] = od; bI[s] = oi; }
        }
    }

    if ((lane & 3) == 0) {
#pragma unroll
        for (int s = 0; s < 4; s++) {
            int row = rowbase + wy * 32 + (lane >> 2) + ((s & 1) ? 8 : 0) + (s >> 1) * 16;
            uint32_t u = __float_as_uint(bD[s]);
            u = (u & 0x80000000u) ? ~u : (u | 0x80000000u);
            unsigned long long key = ((unsigned long long)u << 32) | (unsigned)bI[s];
            atomicMin(&g_best[row], key);
        }
    }
}

// ---------------------------------------------------------------------------
// gather (R12 best, 512 thr) + fused histogram: phase-1 row loaders also
// bump g_cnt (32 spread ATOMG per block, hidden under the row loads).
// ---------------------------------------------------------------------------
__global__ void __launch_bounds__(512) gather_kernel(const float* __restrict__ cb,
                                                     float* __restrict__ out) {
    __shared__ float4 srow[32 * 128];   // 64KB, cf ^ (nl&7) swizzle

    int tid = threadIdx.x;
    int lane = tid & 31;
    int w = tid >> 5;           // 0..15
    int nbase = blockIdx.x * 32;

    // Phase 1: warp w loads rows nl = w*2, w*2+1 (2KB each, coalesced)
#pragma unroll
    for (int k = 0; k < 2; k++) {
        int nl = w * 2 + k;
        int idx = (int)(unsigned)(g_best[nbase + nl] & 0xffffffffu);
        if (lane == 0) atomicAdd(&g_cnt[idx], 1);
        const float4* src = (const float4*)cb + idx * 128;
        int sw = nl & 7;
#pragma unroll
        for (int j = 0; j < 4; j++) {
            int cf = lane + j * 32;
            srow[nl * 128 + (cf ^ sw)] = __ldg(src + cf);
        }
    }
    __syncthreads();

    // Phase 2: lane = row, warp = channel group (8 cf each); streaming stores
    {
        int nl = lane;
        int n = nbase + nl;
        int b = n >> 10, p = n & 1023;
        int sw = nl & 7;
        float* obase = out + ((size_t)b * 512) * 1024 + p;
#pragma unroll
        for (int j = 0; j < 8; j++) {
            int cf = w * 8 + j;
            float4 v = srow[nl * 128 + (cf ^ sw)];
            float* o = obase + (size_t)(cf * 4) * 1024;
            __stcs(o,        v.x);
            __stcs(o + 1024, v.y);
            __stcs(o + 2048, v.z);
            __stcs(o + 3072, v.w);
        }
    }
}

// ---------------------------------------------------------------------------
__global__ void entropy_kernel(float* __restrict__ out_scalars) {
    __shared__ float s[256];
    int tid = threadIdx.x;
    float acc = 0.0f;
    for (int k = tid; k < KK; k += 256) {
        int c = g_cnt[k];
        if (c > 0) {
            float p = (float)c / 32768.0f;
            acc += p * logf(p);
        }
    }
    s[tid] = acc;
    __syncthreads();
    for (int o = 128; o > 0; o >>= 1) {
        if (tid < o) s[tid] += s[tid + o];
        __syncthreads();
    }
    if (tid == 0) {
        float entropy = -s[0];
        float perp = expf(entropy);
        float pl = 1.0f / perp;
        out_scalars[0] = pl;
        out_scalars[1] = 0.25f * pl;
    }
}

// ---------------------------------------------------------------------------
extern "C" void kernel_launch(void* const* d_in, const int* in_sizes, int n_in,
                              void* d_out, int out_size) {
    const float* x  = (const float*)d_in[0];
    const float* cb = (const float*)d_in[1];
    float* out = (float*)d_out;

    cudaFuncSetAttribute(prep_kernel, cudaFuncAttributeMaxDynamicSharedMemorySize, PREP_SMEM);
    cudaFuncSetAttribute(gemm_hmma_kernel, cudaFuncAttributeMaxDynamicSharedMemorySize, GEMM_SMEM);

    init_cb_kernel<<<1024, 256>>>(cb);
    prep_kernel<<<1024, 512, PREP_SMEM>>>(x);
    gemm_hmma_kernel<<<(NN / M_TILE) * (KK / N_TILE), 256, GEMM_SMEM>>>();
    gather_kernel<<<NN / 32, 512>>>(cb, out);
    if (out_size >= QE + 2) {
        entropy_kernel<<<1, 256>>>(out + QE);
    }
}

// round 17
// speedup vs baseline: 1.0408x; 1.0083x over previous
#include <cuda_runtime.h>
#include <cuda_fp16.h>
#include <cstdint>
#include <math.h>

// Problem constants
#define NN   32768
#define KK   1024
#define QE   16777216

// GEMM tiling (R12 best): CTA = 128 rows x 128 codes, 256 thr = 8 warps (4M x 2N)
#define M_TILE 128
#define N_TILE 128
#define K_SLABS 16             // 512 ch / 32 per slab
#define ROW_STRIDE 80          // 64B data + 16B pad (conflict-free ldsm)
#define A_PHASE_BYTES (128 * ROW_STRIDE)            // 10240
#define STAGE_BYTES (3 * A_PHASE_BYTES)             // 2 A planes + B = 30720
#define N_STAGES 3
#define GEMM_SMEM (N_STAGES * STAGE_BYTES)          // 92160 (x2 CTAs/SM)
#define PREP_SMEM (65664 + 2048)

// Scratch (device globals; allocation-free). Slab-major:
__device__ uint32_t g_hi[16 * NN * 16];
__device__ uint32_t g_mid[16 * NN * 16];
__device__ uint32_t g_cbh[16 * KK * 16];   // fp16 codebook [slab][code][16 u32]
__device__ float g_x2[NN];
__device__ unsigned long long g_best[NN];
__device__ int g_cnt[KK];

__device__ __forceinline__ uint32_t smem_u32(const void* p) {
    return (uint32_t)__cvta_generic_to_shared(p);
}

#define LDSM4(r0, r1, r2, r3, addr)                                           \
    asm volatile("ldmatrix.sync.aligned.m8n8.x4.shared.b16 {%0,%1,%2,%3}, [%4];" \
                 : "=r"(r0), "=r"(r1), "=r"(r2), "=r"(r3) : "r"(addr))

#define MMA16816(C, A, B0, B1)                                                \
    asm volatile("mma.sync.aligned.m16n8k16.row.col.f32.f16.f16.f32 "         \
                 "{%0,%1,%2,%3},{%4,%5,%6,%7},{%8,%9},{%0,%1,%2,%3};"         \
                 : "+f"((C)[0]), "+f"((C)[1]), "+f"((C)[2]), "+f"((C)[3])     \
                 : "r"((A)[0]), "r"((A)[1]), "r"((A)[2]), "r"((A)[3]),        \
                   "r"(B0), "r"(B1))

#define CP_ASYNC16(dst, src)                                                  \
    asm volatile("cp.async.cg.shared.global [%0], [%1], 16;" :: "r"(dst), "l"(src))
#define CP_COMMIT() asm volatile("cp.async.commit_group;")
#define CP_WAIT1()  asm volatile("cp.async.wait_group 1;")
#define CP_WAIT0()  asm volatile("cp.async.wait_group 0;")

// ---------------------------------------------------------------------------
// prep: fused init (codebook->fp16 slab-major, g_best, g_cnt) + xs = tanh(50x)
// via FMA-only exp2 + Newton rcp, 2-way fp16 split, transpose slab-major,
// ||xs||^2 + 512.  1024 blocks x 512 threads; block owns rows nb..nb+31.
// ---------------------------------------------------------------------------
__global__ void __launch_bounds__(512, 3) prep_kernel(const float* __restrict__ x,
                                                      const float* __restrict__ cb) {
    extern __shared__ char sm[];
    uint32_t* s_hm = (uint32_t*)sm;             // [32][513]  (hi | mid<<16)
    float* s_red = (float*)(sm + 65664);        // [512]

    int tid = threadIdx.x;
    int b   = blockIdx.x >> 5;
    int p0  = (blockIdx.x & 31) * 32;
    int p   = tid & 31;
    int cg  = tid >> 5;         // 0..15

    // --- fused init: exact, disjoint-by-statement ranges ---
    if (tid < 256) {
        int i = blockIdx.x * 256 + tid;        // 0..262143: code*256 + cw
        int code = i >> 8, cw = i & 255;
        float2 v = ((const float2*)cb)[i];
        __half2 h2 = __floats2half2_rn(v.x, v.y);
        uint32_t u; memcpy(&u, &h2, 4);
        g_cbh[(((size_t)(cw >> 4)) * KK + code) * 16 + (cw & 15)] = u;
    } else {
        if (tid < 288)
            g_best[b * 1024 + p0 + (tid - 256)] = 0xFFFFFFFFFFFFFFFFull;
        if (blockIdx.x < 4)                    // tid-256 covers full [0,256)
            g_cnt[blockIdx.x * 256 + (tid - 256)] = 0;
    }

    float acc = 0.0f;
#pragma unroll 4
    for (int j = 0; j < 32; j++) {
        int c = j * 16 + cg;
        float v = x[(b * 512 + c) * 1024 + p0 + p];
        float t = fmaxf(-144.26950408889634f * fabsf(v), -30.0f);
        float kf = t + 12582912.0f;
        int   ni = __float_as_int(kf) - 0x4B400000;
        float f  = t - (kf - 12582912.0f);
        float pe = 1.52527338e-5f;
        pe = fmaf(pe, f, 1.54035304e-4f);
        pe = fmaf(pe, f, 1.33335581e-3f);
        pe = fmaf(pe, f, 9.61812911e-3f);
        pe = fmaf(pe, f, 5.55041087e-2f);
        pe = fmaf(pe, f, 2.40226507e-1f);
        pe = fmaf(pe, f, 6.93147181e-1f);
        pe = fmaf(pe, f, 1.0f);
        float m = __int_as_float(__float_as_int(pe) + (ni << 23));
        float den = 1.0f + m;
        float r = fmaf(-0.5f, den, 1.45710678f);
        r = r * fmaf(-den, r, 2.0f);
        r = r * fmaf(-den, r, 2.0f);
        r = r * fmaf(-den, r, 2.0f);
        float w = (1.0f - m) * r;
        float xs = copysignf(w, v);
        acc = fmaf(w, w, acc);
        __half h = __float2half_rn(xs);
        float r1 = xs - __half2float(h);
        __half md = __float2half_rn(r1);
        s_hm[p * 513 + c] = (uint32_t)__half_as_ushort(h)
                          | ((uint32_t)__half_as_ushort(md) << 16);
    }
    s_red[tid] = acc;
    __syncthreads();

    if (tid < 32) {
        float t = 0.0f;
#pragma unroll
        for (int g = 0; g < 16; g++) t += s_red[g * 32 + tid];
        g_x2[b * 1024 + p0 + tid] = t + 512.0f;
    }

    int nb = b * 1024 + p0;
#pragma unroll 4
    for (int t = tid; t < 32 * 256; t += 512) {
        int r  = t >> 8;
        int cw = t & 255;
        uint32_t hm0 = s_hm[r * 513 + 2 * cw];
        uint32_t hm1 = s_hm[r * 513 + 2 * cw + 1];
        uint32_t hi_pair  = (hm0 & 0xffffu) | (hm1 << 16);
        uint32_t mid_pair = (hm0 >> 16) | (hm1 & 0xffff0000u);
        size_t gi = (((size_t)(cw >> 4)) * NN + nb + r) * 16 + (cw & 15);
        g_hi[gi]  = hi_pair;
        g_mid[gi] = mid_pair;
    }
}

// ---------------------------------------------------------------------------
// GEMM + fused argmin (R12 best). grid = 256 M-tiles x 8 N-chunks.
// 256 threads = 8 warps (4M x 2N), warp tile 32x64, 2 fp16 split planes.
// 3-stage cp.async pipeline, one __syncthreads per slab, 2 CTAs/SM.
// ---------------------------------------------------------------------------
__global__ void __launch_bounds__(256, 2) gemm_hmma_kernel() {
    extern __shared__ char sm[];
    uint32_t smb = smem_u32(sm);

    int tid = threadIdx.x;
    int lane = tid & 31;
    int wid = tid >> 5;
    int wy = wid & 3;
    int wx = wid >> 2;          // 0..1
    int bid = blockIdx.x;
    int rowbase = (bid >> 3) * M_TILE;
    int colchunk = (bid & 7) * N_TILE;

    uint32_t tbaseA = (uint32_t)((wy * 32 + ((lane >> 3) & 1) * 8 + (lane & 7)) * ROW_STRIDE
                                 + (lane >> 4) * 16);
    uint32_t tbaseB = (uint32_t)(((lane >> 4) * 8 + (lane & 7)) * ROW_STRIDE
                                 + ((lane >> 3) & 1) * 16);

    const char* gA[2] = { (const char*)g_hi, (const char*)g_mid };

    float x2v[4];
#pragma unroll
    for (int s = 0; s < 4; s++)
        x2v[s] = g_x2[rowbase + wy * 32 + (lane >> 2) + ((s & 1) ? 8 : 0) + (s >> 1) * 16];

    float bD[4] = {INFINITY, INFINITY, INFINITY, INFINITY};
    int   bI[4] = {0, 0, 0, 0};

    float acc[2][8][4];
#pragma unroll
    for (int m = 0; m < 2; m++)
#pragma unroll
        for (int nf = 0; nf < 8; nf++)
#pragma unroll
            for (int j = 0; j < 4; j++) acc[m][nf][j] = 0.0f;

// 1536 16B chunks per slab: A 2 planes x128r x4c = 1024, B 128r x4c = 512.
#define ISSUE_SLAB(slab, stage)                                               \
    {                                                                         \
        uint32_t dstbase = smb + (stage) * STAGE_BYTES;                       \
        _Pragma("unroll")                                                     \
        for (int i = 0; i < 6; i++) {                                         \
            int id = tid + i * 256;                                           \
            if (id < 1024) {                                                  \
                int part = id >> 9;                                           \
                int r = (id >> 2) & 127;                                      \
                int c = id & 3;                                               \
                uint32_t dst = dstbase + part * A_PHASE_BYTES                 \
                             + r * ROW_STRIDE + c * 16;                       \
                const char* src = gA[part]                                    \
                    + ((size_t)(slab) * NN + rowbase + r) * 64 + c * 16;      \
                CP_ASYNC16(dst, src);                                         \
            } else {                                                          \
                int id2 = id - 1024;                                          \
                int r = id2 >> 2;                                             \
                int c = id2 & 3;                                              \
                uint32_t dst = dstbase + 2 * A_PHASE_BYTES                    \
                             + r * ROW_STRIDE + c * 16;                       \
                const char* src = (const char*)g_cbh                          \
                    + ((size_t)(slab) * KK + colchunk + r) * 64 + c * 16;     \
                CP_ASYNC16(dst, src);                                         \
            }                                                                 \
        }                                                                     \
        CP_COMMIT();                                                          \
    }

    // prologue: two slabs in flight
    ISSUE_SLAB(0, 0);
    ISSUE_SLAB(1, 1);

    int st0 = 0;                // stage of slab s
    for (int s = 0; s < K_SLABS; s++) {
        if (s + 1 < K_SLABS) { CP_WAIT1(); } else { CP_WAIT0(); }
        __syncthreads();

        // issue s+2 into the stage freed by slab s-1 (readers done at the sync)
        if (s + 2 < K_SLABS) {
            int st2 = st0 + 2; if (st2 >= N_STAGES) st2 -= N_STAGES;
            ISSUE_SLAB(s + 2, st2);
        }

        uint32_t sA = smb + st0 * STAGE_BYTES;
        uint32_t sB = sA + 2 * A_PHASE_BYTES;
#pragma unroll
        for (int kk = 0; kk < 2; kk++) {
            uint32_t b[8][2];
#pragma unroll
            for (int q = 0; q < 4; q++) {
                uint32_t addr = sB + (uint32_t)((wx * 64 + q * 16) * ROW_STRIDE)
                              + tbaseB + kk * 32;
                LDSM4(b[2 * q][0], b[2 * q][1], b[2 * q + 1][0], b[2 * q + 1][1], addr);
            }
#pragma unroll
            for (int p = 0; p < 2; p++) {
                uint32_t a0[4], a1[4];
                uint32_t aaddr = sA + p * A_PHASE_BYTES + tbaseA + kk * 32;
                LDSM4(a0[0], a0[1], a0[2], a0[3], aaddr);
                LDSM4(a1[0], a1[1], a1[2], a1[3], aaddr + 16 * ROW_STRIDE);
#pragma unroll
                for (int nf = 0; nf < 8; nf++) {
                    MMA16816(acc[0][nf], a0, b[nf][0], b[nf][1]);
                    MMA16816(acc[1][nf], a1, b[nf][0], b[nf][1]);
                }
            }
        }
        st0 = st0 + 1; if (st0 >= N_STAGES) st0 -= N_STAGES;
    }
#undef ISSUE_SLAB

    // fused argmin over this chunk's 128 columns (ascending index)
    int colbase = colchunk + wx * 64 + (lane & 3) * 2;
#pragma unroll
    for (int nf = 0; nf < 8; nf++) {
        int cidx = colbase + nf * 8;
#pragma unroll
        for (int m = 0; m < 2; m++) {
            float d0 = fmaf(-2.0f, acc[m][nf][0], x2v[m * 2]);
            float d1 = fmaf(-2.0f, acc[m][nf][1], x2v[m * 2]);
            float d2 = fmaf(-2.0f, acc[m][nf][2], x2v[m * 2 + 1]);
            float d3 = fmaf(-2.0f, acc[m][nf][3], x2v[m * 2 + 1]);
            if (d0 < bD[m * 2])     { bD[m * 2] = d0;     bI[m * 2] = cidx; }
            if (d1 < bD[m * 2])     { bD[m * 2] = d1;     bI[m * 2] = cidx + 1; }
            if (d2 < bD[m * 2 + 1]) { bD[m * 2 + 1] = d2; bI[m * 2 + 1] = cidx; }
            if (d3 < bD[m * 2 + 1]) { bD[m * 2 + 1] = d3; bI[m * 2 + 1] = cidx + 1; }
        }
    }

#pragma unroll
    for (int off = 1; off <= 2; off <<= 1) {
#pragma unroll
        for (int s = 0; s < 4; s++) {
            float od = __shfl_xor_sync(0xffffffffu, bD[s], off);
            int   oi = __shfl_xor_sync(0xffffffffu, bI[s], off);
            if (od < bD[s] || (od == bD[s] && oi < bI[s])) { bD[s] = od; bI[s] = oi; }
        }
    }

    if ((lane & 3) == 0) {
#pragma unroll
        for (int s = 0; s < 4; s++) {
            int row = rowbase + wy * 32 + (lane >> 2) + ((s & 1) ? 8 : 0) + (s >> 1) * 16;
            uint32_t u = __float_as_uint(bD[s]);
            u = (u & 0x80000000u) ? ~u : (u | 0x80000000u);
            unsigned long long key = ((unsigned long long)u << 32) | (unsigned)bI[s];
            atomicMin(&g_best[row], key);
        }
    }
}

// ---------------------------------------------------------------------------
// gather (best config) + fused histogram.
// ---------------------------------------------------------------------------
__global__ void __launch_bounds__(512) gather_kernel(const float* __restrict__ cb,
                                                     float* __restrict__ out) {
    __shared__ float4 srow[32 * 128];   // 64KB, cf ^ (nl&7) swizzle

    int tid = threadIdx.x;
    int lane = tid & 31;
    int w = tid >> 5;           // 0..15
    int nbase = blockIdx.x * 32;

    // Phase 1: warp w loads rows nl = w*2, w*2+1 (2KB each, coalesced)
    int idx0 = (int)(unsigned)(g_best[nbase + w * 2]     & 0xffffffffu);
    int idx1 = (int)(unsigned)(g_best[nbase + w * 2 + 1] & 0xffffffffu);
    if (lane == 0) atomicAdd(&g_cnt[idx0], 1);
    if (lane == 1) atomicAdd(&g_cnt[idx1], 1);
    int idxs[2] = { idx0, idx1 };
#pragma unroll
    for (int k = 0; k < 2; k++) {
        int nl = w * 2 + k;
        const float4* src = (const float4*)cb + idxs[k] * 128;
        int sw = nl & 7;
#pragma unroll
        for (int j = 0; j < 4; j++) {
            int cf = lane + j * 32;
            srow[nl * 128 + (cf ^ sw)] = __ldg(src + cf);
        }
    }
    __syncthreads();

    // Phase 2: lane = row, warp = channel group (8 cf each); streaming stores
    {
        int nl = lane;
        int n = nbase + nl;
        int b = n >> 10, p = n & 1023;
        int sw = nl & 7;
        float* obase = out + ((size_t)b * 512) * 1024 + p;
#pragma unroll
        for (int j = 0; j < 8; j++) {
            int cf = w * 8 + j;
            float4 v = srow[nl * 128 + (cf ^ sw)];
            float* o = obase + (size_t)(cf * 4) * 1024;
            __stcs(o,        v.x);
            __stcs(o + 1024, v.y);
            __stcs(o + 2048, v.z);
            __stcs(o + 3072, v.w);
        }
    }
}

// ---------------------------------------------------------------------------
__global__ void entropy_kernel(float* __restrict__ out_scalars) {
    __shared__ float s[256];
    int tid = threadIdx.x;
    float acc = 0.0f;
    for (int k = tid; k < KK; k += 256) {
        int c = g_cnt[k];
        if (c > 0) {
            float p = (float)c / 32768.0f;
            acc += p * logf(p);
        }
    }
    s[tid] = acc;
    __syncthreads();
    for (int o = 128; o > 0; o >>= 1) {
        if (tid < o) s[tid] += s[tid + o];
        __syncthreads();
    }
    if (tid == 0) {
        float entropy = -s[0];
        float perp = expf(entropy);
        float pl = 1.0f / perp;
        out_scalars[0] = pl;
        out_scalars[1] = 0.25f * pl;
    }
}

// ---------------------------------------------------------------------------
extern "C" void kernel_launch(void* const* d_in, const int* in_sizes, int n_in,
                              void* d_out, int out_size) {
    const float* x  = (const float*)d_in[0];
    const float* cb = (const float*)d_in[1];
    float* out = (float*)d_out;

    cudaFuncSetAttribute(prep_kernel, cudaFuncAttributeMaxDynamicSharedMemorySize, PREP_SMEM);
    cudaFuncSetAttribute(gemm_hmma_kernel, cudaFuncAttributeMaxDynamicSharedMemorySize, GEMM_SMEM);

    prep_kernel<<<1024, 512, PREP_SMEM>>>(x, cb);
    gemm_hmma_kernel<<<(NN / M_TILE) * (KK / N_TILE), 256, GEMM_SMEM>>>();
    gather_kernel<<<NN / 32, 512>>>(cb, out);
    if (out_size >= QE + 2) {
        entropy_kernel<<<1, 256>>>(out + QE);
    }
}